// round 1
// baseline (speedup 1.0000x reference)
#include <cuda_runtime.h>
#include <cuda_bf16.h>
#include <cstdint>

// Problem constants
#define B_DIM 4096
#define D_DIM 1024
#define H_DIM 1024
#define N_GATES 4096   // 4*H
#define K_DIM  2048    // D + H

// GEMM tiling
#define BM 128
#define BN 128
#define BK 8
#define TM 8
#define TN 8
#define NTHREADS 256

// Scratch for the pre-activation gates: [B, 4H] fp32 = 64 MB.
// __device__ global (module-load allocated) — satisfies the no-alloc rule.
__device__ float g_gates[(size_t)B_DIM * N_GATES];

// ---------------------------------------------------------------------------
// Kernel 1: gates = [x | h] @ [w_ih | w_hh]^T
//   A: M=4096 rows (batch), K=2048 (first 1024 from x, next 1024 from h)
//   B: N=4096 rows (gate-cols), K=2048 (first 1024 from w_ih, next from w_hh)
// Classic 128x128x8 register-blocked SGEMM, 8x8 per thread.
// ---------------------------------------------------------------------------
__global__ __launch_bounds__(NTHREADS, 2)
void lstm_gemm_gates(const float* __restrict__ x,
                     const float* __restrict__ h0,
                     const float* __restrict__ wih,
                     const float* __restrict__ whh)
{
    __shared__ float As[BK][BM];   // transposed A tile: As[k][m]
    __shared__ float Bs[BK][BN];   // transposed B tile: Bs[k][n]

    const int tid = threadIdx.x;
    const int block_row = blockIdx.y * BM;   // batch base
    const int block_col = blockIdx.x * BN;   // gate-col base

    // Global->shared load mapping: each thread loads one float4 of A and one of B.
    // 128 rows x 8 k = 1024 floats = 256 threads * 4.
    const int ld_row  = tid >> 1;          // 0..127
    const int ld_koff = (tid & 1) * 4;     // 0 or 4

    // Compute mapping: 16x16 thread grid, each owns TMxTN micro-tile.
    const int trow = (tid >> 4) * TM;      // 0..120
    const int tcol = (tid & 15) * TN;      // 0..120

    float acc[TM][TN];
    #pragma unroll
    for (int i = 0; i < TM; i++)
        #pragma unroll
        for (int j = 0; j < TN; j++)
            acc[i][j] = 0.0f;

    float a_frag[TM];
    float b_frag[TN];

    for (int k0 = 0; k0 < K_DIM; k0 += BK) {
        // ---- load A tile (x for k<1024, h for k>=1024; BK divides 1024) ----
        {
            const float* Asrc = (k0 < D_DIM) ? x : h0;
            const int    ak   = (k0 < D_DIM) ? k0 : (k0 - D_DIM);
            float4 av = *reinterpret_cast<const float4*>(
                &Asrc[(size_t)(block_row + ld_row) * D_DIM + ak + ld_koff]);
            As[ld_koff + 0][ld_row] = av.x;
            As[ld_koff + 1][ld_row] = av.y;
            As[ld_koff + 2][ld_row] = av.z;
            As[ld_koff + 3][ld_row] = av.w;
        }
        // ---- load B tile (w_ih / w_hh) ----
        {
            const float* Bsrc = (k0 < D_DIM) ? wih : whh;
            const int    bk   = (k0 < D_DIM) ? k0 : (k0 - D_DIM);
            float4 bv = *reinterpret_cast<const float4*>(
                &Bsrc[(size_t)(block_col + ld_row) * D_DIM + bk + ld_koff]);
            Bs[ld_koff + 0][ld_row] = bv.x;
            Bs[ld_koff + 1][ld_row] = bv.y;
            Bs[ld_koff + 2][ld_row] = bv.z;
            Bs[ld_koff + 3][ld_row] = bv.w;
        }
        __syncthreads();

        #pragma unroll
        for (int kk = 0; kk < BK; kk++) {
            // vectorized shared reads
            float4 a0 = *reinterpret_cast<const float4*>(&As[kk][trow]);
            float4 a1 = *reinterpret_cast<const float4*>(&As[kk][trow + 4]);
            a_frag[0] = a0.x; a_frag[1] = a0.y; a_frag[2] = a0.z; a_frag[3] = a0.w;
            a_frag[4] = a1.x; a_frag[5] = a1.y; a_frag[6] = a1.z; a_frag[7] = a1.w;
            float4 b0 = *reinterpret_cast<const float4*>(&Bs[kk][tcol]);
            float4 b1 = *reinterpret_cast<const float4*>(&Bs[kk][tcol + 4]);
            b_frag[0] = b0.x; b_frag[1] = b0.y; b_frag[2] = b0.z; b_frag[3] = b0.w;
            b_frag[4] = b1.x; b_frag[5] = b1.y; b_frag[6] = b1.z; b_frag[7] = b1.w;

            #pragma unroll
            for (int i = 0; i < TM; i++)
                #pragma unroll
                for (int j = 0; j < TN; j++)
                    acc[i][j] = fmaf(a_frag[i], b_frag[j], acc[i][j]);
        }
        __syncthreads();
    }

    // ---- write gates (vectorized) ----
    #pragma unroll
    for (int i = 0; i < TM; i++) {
        const size_t row = (size_t)(block_row + trow + i);
        float* dst = &g_gates[row * N_GATES + block_col + tcol];
        float4 v0 = make_float4(acc[i][0], acc[i][1], acc[i][2], acc[i][3]);
        float4 v1 = make_float4(acc[i][4], acc[i][5], acc[i][6], acc[i][7]);
        *reinterpret_cast<float4*>(dst)     = v0;
        *reinterpret_cast<float4*>(dst + 4) = v1;
    }
}

// ---------------------------------------------------------------------------
// Kernel 2: epilogue — bias + activations + cell/hidden update.
//   i = gates[b, j],  f = gates[b, H+j],  g = gates[b, 2H+j],  o = gates[b, 3H+j]
//   c = sigmoid(f)*c0 + sigmoid(i)*tanh(g);  h = sigmoid(o)*tanh(c)
//   out[0 .. B*H)      = h
//   out[B*H .. 2*B*H)  = c
// ---------------------------------------------------------------------------
__device__ __forceinline__ float sigmoidf_(float v) {
    return 1.0f / (1.0f + __expf(-v));
}

__global__ __launch_bounds__(256)
void lstm_epilogue(const float* __restrict__ c0,
                   const float* __restrict__ b_ih,
                   const float* __restrict__ b_hh,
                   float* __restrict__ out)
{
    const int idx = blockIdx.x * blockDim.x + threadIdx.x;   // 0 .. B*H
    const int b = idx >> 10;          // / H
    const int j = idx & (H_DIM - 1);  // % H

    const float* grow = g_gates + (size_t)b * N_GATES;
    const float gi = grow[j]              + b_ih[j]              + b_hh[j];
    const float gf = grow[H_DIM + j]      + b_ih[H_DIM + j]      + b_hh[H_DIM + j];
    const float gg = grow[2 * H_DIM + j]  + b_ih[2 * H_DIM + j]  + b_hh[2 * H_DIM + j];
    const float go = grow[3 * H_DIM + j]  + b_ih[3 * H_DIM + j]  + b_hh[3 * H_DIM + j];

    const float c_new = sigmoidf_(gf) * c0[idx] + sigmoidf_(gi) * tanhf(gg);
    const float h_new = sigmoidf_(go) * tanhf(c_new);

    out[idx] = h_new;
    out[(size_t)B_DIM * H_DIM + idx] = c_new;
}

// ---------------------------------------------------------------------------
// Launch
// ---------------------------------------------------------------------------
extern "C" void kernel_launch(void* const* d_in, const int* in_sizes, int n_in,
                              void* d_out, int out_size)
{
    const float* x    = (const float*)d_in[0];   // [4096, 1024]
    const float* h0   = (const float*)d_in[1];   // [1, 4096, 1024]
    const float* c0   = (const float*)d_in[2];   // [1, 4096, 1024]
    const float* wih  = (const float*)d_in[3];   // [4096, 1024]
    const float* whh  = (const float*)d_in[4];   // [4096, 1024]
    const float* b_ih = (const float*)d_in[5];   // [4096]
    const float* b_hh = (const float*)d_in[6];   // [4096]
    float* out = (float*)d_out;                  // [2 * 4096 * 1024]

    dim3 grid(N_GATES / BN, B_DIM / BM);         // (32, 32)
    lstm_gemm_gates<<<grid, NTHREADS>>>(x, h0, wih, whh);

    const int total = B_DIM * H_DIM;             // 4,194,304
    lstm_epilogue<<<total / 256, 256>>>(c0, b_ih, b_hh, out);
}

// round 3
// speedup vs baseline: 2.4623x; 2.4623x over previous
#include <cuda_runtime.h>
#include <cuda_bf16.h>
#include <cstdint>

// ---------------------------------------------------------------------------
// Problem constants
// ---------------------------------------------------------------------------
#define B_DIM 4096
#define H_DIM 1024
#define N_GATES 4096       // 4*H
#define K_DIM  2048        // D + H

// GEMM tiling (mma.sync path — portable to baseline compute_103 target)
#define BM 128
#define BN 128
#define BK 32
#define STAGES 4
#define NT (K_DIM / BK)    // 64 k-tiles
#define NTHREADS 256

// smem layout: per stage 4 tiles (Ahi, Alo, Bhi, Blo), each 128 rows x 32 bf16,
// row stride padded to 40 bf16 = 80 B  ->  tile = 10240 B, stage = 40960 B.
#define TILE_BYTES 10240
#define STAGE_BYTES (4 * TILE_BYTES)
#define SMEM_TOTAL (STAGES * STAGE_BYTES)   // 163840
#define ROW_STRIDE 80                        // bytes

// ---------------------------------------------------------------------------
// Scratch (device globals; no runtime allocation)
// ---------------------------------------------------------------------------
__device__ float g_gates[(size_t)B_DIM * N_GATES];                    // 64 MB
__device__ __nv_bfloat16 gAhi[(size_t)B_DIM * K_DIM];                 // 16 MB each
__device__ __nv_bfloat16 gAlo[(size_t)B_DIM * K_DIM];
__device__ __nv_bfloat16 gBhi[(size_t)N_GATES * K_DIM];
__device__ __nv_bfloat16 gBlo[(size_t)N_GATES * K_DIM];

// ---------------------------------------------------------------------------
// PTX helpers (all baseline sm_80+ portable)
// ---------------------------------------------------------------------------
__device__ __forceinline__ uint32_t smem_u32(const void* p) {
    uint32_t a;
    asm("{ .reg .u64 t; cvta.to.shared.u64 t, %1; cvt.u32.u64 %0, t; }" : "=r"(a) : "l"(p));
    return a;
}

#define CP_ASYNC16(dst, src) \
    asm volatile("cp.async.cg.shared.global [%0], [%1], 16;" \
                 :: "r"(dst), "l"(src) : "memory")
#define CP_COMMIT() asm volatile("cp.async.commit_group;" ::: "memory")
#define CP_WAIT(n)  asm volatile("cp.async.wait_group %0;" :: "n"(n) : "memory")

#define LDSM_X4(r, addr) \
    asm volatile("ldmatrix.sync.aligned.m8n8.x4.shared.b16 {%0,%1,%2,%3}, [%4];" \
                 : "=r"((r)[0]), "=r"((r)[1]), "=r"((r)[2]), "=r"((r)[3]) : "r"(addr))

__device__ __forceinline__ void mma_bf16(float* d, const uint32_t* a, const uint32_t* b) {
    asm volatile(
        "mma.sync.aligned.m16n8k16.row.col.f32.bf16.bf16.f32 "
        "{%0,%1,%2,%3}, {%4,%5,%6,%7}, {%8,%9}, {%0,%1,%2,%3};"
        : "+f"(d[0]), "+f"(d[1]), "+f"(d[2]), "+f"(d[3])
        : "r"(a[0]), "r"(a[1]), "r"(a[2]), "r"(a[3]), "r"(b[0]), "r"(b[1]));
}

// ---------------------------------------------------------------------------
// Kernel: split fp32 pair of [4096,1024] matrices into bf16 hi/lo [4096,2048]
// ---------------------------------------------------------------------------
__global__ __launch_bounds__(256)
void convert_split(const float* __restrict__ s0, const float* __restrict__ s1,
                   __nv_bfloat16* __restrict__ hi, __nv_bfloat16* __restrict__ lo)
{
    const int idx = blockIdx.x * 256 + threadIdx.x;   // group of 4 elems
    const int row = idx >> 9;                         // 512 groups / row
    const int col = (idx & 511) << 2;
    const float* src = (col < 1024) ? (s0 + (size_t)row * 1024 + col)
                                    : (s1 + (size_t)row * 1024 + (col - 1024));
    float4 v = *reinterpret_cast<const float4*>(src);
    float f[4] = {v.x, v.y, v.z, v.w};
    __nv_bfloat16 hb[4], lb[4];
    #pragma unroll
    for (int j = 0; j < 4; j++) {
        hb[j] = __float2bfloat16(f[j]);
        lb[j] = __float2bfloat16(f[j] - __bfloat162float(hb[j]));
    }
    const size_t o = (size_t)row * K_DIM + col;
    *reinterpret_cast<__nv_bfloat162*>(hi + o)     = __nv_bfloat162(hb[0], hb[1]);
    *reinterpret_cast<__nv_bfloat162*>(hi + o + 2) = __nv_bfloat162(hb[2], hb[3]);
    *reinterpret_cast<__nv_bfloat162*>(lo + o)     = __nv_bfloat162(lb[0], lb[1]);
    *reinterpret_cast<__nv_bfloat162*>(lo + o + 2) = __nv_bfloat162(lb[2], lb[3]);
}

// ---------------------------------------------------------------------------
// Stage loader: 4 tiles x 512 16B-chunks = 2048 chunks; 8 per thread.
//   tile 0: Ahi rows bm..bm+127   tile 1: Alo
//   tile 2: Bhi rows bn..bn+127   tile 3: Blo
// ---------------------------------------------------------------------------
__device__ __forceinline__ void load_stage(uint32_t sbase, int k0, int bm, int bn, int tid)
{
    #pragma unroll
    for (int i = 0; i < 8; i++) {
        const int idx  = tid + i * 256;
        const int tile = idx >> 9;            // constant per i-pair
        const int r    = (idx & 511) >> 2;    // 0..127
        const int c    = idx & 3;             // 16B chunk within 64B row
        const __nv_bfloat16* src =
            (tile == 0) ? gAhi : (tile == 1) ? gAlo : (tile == 2) ? gBhi : gBlo;
        const int rowbase = (tile < 2) ? bm : bn;
        const void* g = src + (size_t)(rowbase + r) * K_DIM + k0 + c * 8;
        const uint32_t dst = sbase + tile * TILE_BYTES + r * ROW_STRIDE + c * 16;
        CP_ASYNC16(dst, g);
    }
}

// ---------------------------------------------------------------------------
// GEMM: gates = Ahi*Bhi^T + Ahi*Blo^T + Alo*Bhi^T   (bf16 mma.sync, f32 acc)
// 8 warps: warp_m = wid>>1 (4), warp_n = wid&1 (2); warp tile 32x64.
// ---------------------------------------------------------------------------
__global__ __launch_bounds__(NTHREADS, 1)
void lstm_gemm_mma()
{
    extern __shared__ char smem[];
    const uint32_t sb = smem_u32(smem);
    const int tid  = threadIdx.x;
    const int wid  = tid >> 5;
    const int lane = tid & 31;
    const int warp_m = wid >> 1;    // 0..3
    const int warp_n = wid & 1;     // 0..1

    const int bm = blockIdx.y * BM;
    const int bn = blockIdx.x * BN;

    float acc[2][8][4];
    #pragma unroll
    for (int mt = 0; mt < 2; mt++)
        #pragma unroll
        for (int nt = 0; nt < 8; nt++)
            #pragma unroll
            for (int j = 0; j < 4; j++)
                acc[mt][nt][j] = 0.0f;

    // per-thread ldmatrix row addressing (within a tile)
    const int a_row = warp_m * 32 + (lane & 15);          // + mt*16
    const int a_kby = (lane >> 4) * 16;                   // k half byte offset (8 bf16)
    const int b_nrow = warp_n * 64 + ((lane >> 4) << 3) + (lane & 7);  // + g*16
    const int b_kby  = ((lane >> 3) & 1) * 16;            // byte offset of k octet

    // prologue: fill STAGES-1 stages
    #pragma unroll
    for (int s = 0; s < STAGES - 1; s++) {
        load_stage(sb + s * STAGE_BYTES, s * BK, bm, bn, tid);
        CP_COMMIT();
    }

    for (int t = 0; t < NT; t++) {
        // issue next stage
        if (t + STAGES - 1 < NT)
            load_stage(sb + ((t + STAGES - 1) % STAGES) * STAGE_BYTES,
                       (t + STAGES - 1) * BK, bm, bn, tid);
        CP_COMMIT();
        CP_WAIT(STAGES - 2);
        __syncthreads();

        const uint32_t stage = sb + (t % STAGES) * STAGE_BYTES;
        const uint32_t Ahi_b = stage;
        const uint32_t Bhi_b = stage + 2 * TILE_BYTES;

        #pragma unroll
        for (int ks = 0; ks < 2; ks++) {
            uint32_t a_hi[2][4], a_lo[2][4], b_hi[4][4], b_lo[4][4];
            #pragma unroll
            for (int mt = 0; mt < 2; mt++) {
                const uint32_t aa = Ahi_b + (a_row + mt * 16) * ROW_STRIDE + ks * 32 + a_kby;
                LDSM_X4(a_hi[mt], aa);
                LDSM_X4(a_lo[mt], aa + TILE_BYTES);
            }
            #pragma unroll
            for (int g = 0; g < 4; g++) {
                const uint32_t ba = Bhi_b + (b_nrow + g * 16) * ROW_STRIDE + ks * 32 + b_kby;
                LDSM_X4(b_hi[g], ba);
                LDSM_X4(b_lo[g], ba + TILE_BYTES);
            }
            #pragma unroll
            for (int mt = 0; mt < 2; mt++)
                #pragma unroll
                for (int nt = 0; nt < 8; nt++) {
                    const uint32_t* bh = &b_hi[nt >> 1][(nt & 1) * 2];
                    const uint32_t* bl = &b_lo[nt >> 1][(nt & 1) * 2];
                    mma_bf16(acc[mt][nt], a_hi[mt], bh);
                    mma_bf16(acc[mt][nt], a_hi[mt], bl);
                    mma_bf16(acc[mt][nt], a_lo[mt], bh);
                }
        }
        __syncthreads();
    }

    // write accumulators: thread lane -> (row = i>>2, colpair = (i&3)*2), rows +8 for d2,d3
    #pragma unroll
    for (int mt = 0; mt < 2; mt++) {
        const int r0 = bm + warp_m * 32 + mt * 16 + (lane >> 2);
        #pragma unroll
        for (int nt = 0; nt < 8; nt++) {
            const int cc = bn + warp_n * 64 + nt * 8 + (lane & 3) * 2;
            float2* p0 = reinterpret_cast<float2*>(&g_gates[(size_t)r0 * N_GATES + cc]);
            float2* p1 = reinterpret_cast<float2*>(&g_gates[(size_t)(r0 + 8) * N_GATES + cc]);
            *p0 = make_float2(acc[mt][nt][0], acc[mt][nt][1]);
            *p1 = make_float2(acc[mt][nt][2], acc[mt][nt][3]);
        }
    }
}

// ---------------------------------------------------------------------------
// Epilogue: bias + activations + cell/hidden update
// ---------------------------------------------------------------------------
__device__ __forceinline__ float sigmoidf_(float v) {
    return 1.0f / (1.0f + __expf(-v));
}

__global__ __launch_bounds__(256)
void lstm_epilogue(const float* __restrict__ c0,
                   const float* __restrict__ b_ih,
                   const float* __restrict__ b_hh,
                   float* __restrict__ out)
{
    const int idx = blockIdx.x * blockDim.x + threadIdx.x;   // 0 .. B*H
    const int b = idx >> 10;
    const int j = idx & (H_DIM - 1);

    const float* grow = g_gates + (size_t)b * N_GATES;
    const float gi = grow[j]             + b_ih[j]             + b_hh[j];
    const float gf = grow[H_DIM + j]     + b_ih[H_DIM + j]     + b_hh[H_DIM + j];
    const float gg = grow[2 * H_DIM + j] + b_ih[2 * H_DIM + j] + b_hh[2 * H_DIM + j];
    const float go = grow[3 * H_DIM + j] + b_ih[3 * H_DIM + j] + b_hh[3 * H_DIM + j];

    const float c_new = sigmoidf_(gf) * c0[idx] + sigmoidf_(gi) * tanhf(gg);
    const float h_new = sigmoidf_(go) * tanhf(c_new);

    out[idx] = h_new;
    out[(size_t)B_DIM * H_DIM + idx] = c_new;
}

// ---------------------------------------------------------------------------
// Launch
// ---------------------------------------------------------------------------
extern "C" void kernel_launch(void* const* d_in, const int* in_sizes, int n_in,
                              void* d_out, int out_size)
{
    const float* x    = (const float*)d_in[0];
    const float* h0   = (const float*)d_in[1];
    const float* c0   = (const float*)d_in[2];
    const float* wih  = (const float*)d_in[3];
    const float* whh  = (const float*)d_in[4];
    const float* b_ih = (const float*)d_in[5];
    const float* b_hh = (const float*)d_in[6];
    float* out = (float*)d_out;

    cudaFuncSetAttribute(lstm_gemm_mma,
                         cudaFuncAttributeMaxDynamicSharedMemorySize, SMEM_TOTAL);

    __nv_bfloat16 *ahi, *alo, *bhi, *blo;
    cudaGetSymbolAddress((void**)&ahi, gAhi);
    cudaGetSymbolAddress((void**)&alo, gAlo);
    cudaGetSymbolAddress((void**)&bhi, gBhi);
    cudaGetSymbolAddress((void**)&blo, gBlo);

    const int conv_blocks = (B_DIM * K_DIM / 4) / 256;   // 8192
    convert_split<<<conv_blocks, 256>>>(x, h0, ahi, alo);
    convert_split<<<conv_blocks, 256>>>(wih, whh, bhi, blo);

    dim3 grid(N_GATES / BN, B_DIM / BM);                 // (32, 32)
    lstm_gemm_mma<<<grid, NTHREADS, SMEM_TOTAL>>>();

    const int total = B_DIM * H_DIM;
    lstm_epilogue<<<total / 256, 256>>>(c0, b_ih, b_hh, out);
}

// round 4
// speedup vs baseline: 2.9760x; 1.2086x over previous
#include <cuda_runtime.h>
#include <cuda_bf16.h>
#include <cstdint>

// ---------------------------------------------------------------------------
// Problem constants
// ---------------------------------------------------------------------------
#define B_DIM 4096
#define H_DIM 1024
#define N_GATES 4096       // 4*H
#define K_DIM  2048        // D + H

// GEMM tiling
#define BM 128
#define BN 128
#define BK 32
#define STAGES 2
#define NT (K_DIM / BK)    // 64 k-tiles
#define NTHREADS 256

// smem: per stage 4 tiles (Ahi, Alo, Bhi, Blo): 128 rows x 32 bf16, row pad 80B.
#define TILE_BYTES 10240
#define STAGE_BYTES (4 * TILE_BYTES)
#define SMEM_TOTAL (STAGES * STAGE_BYTES)   // 81920 -> 2 CTAs/SM
#define ROW_STRIDE 80

// ---------------------------------------------------------------------------
// Scratch (device globals; no runtime allocation)
// gB* hold the GATE-INTERLEAVED weight layout: row n' = j*4 + g  (orig g*H + j)
// ---------------------------------------------------------------------------
__device__ __nv_bfloat16 gAhi[(size_t)B_DIM * K_DIM];
__device__ __nv_bfloat16 gAlo[(size_t)B_DIM * K_DIM];
__device__ __nv_bfloat16 gBhi[(size_t)N_GATES * K_DIM];
__device__ __nv_bfloat16 gBlo[(size_t)N_GATES * K_DIM];
__device__ float gBias[N_GATES];   // permuted b_ih + b_hh

// ---------------------------------------------------------------------------
// PTX helpers (sm_80+ portable)
// ---------------------------------------------------------------------------
__device__ __forceinline__ uint32_t smem_u32(const void* p) {
    uint32_t a;
    asm("{ .reg .u64 t; cvta.to.shared.u64 t, %1; cvt.u32.u64 %0, t; }" : "=r"(a) : "l"(p));
    return a;
}

#define CP_ASYNC16(dst, src) \
    asm volatile("cp.async.cg.shared.global [%0], [%1], 16;" \
                 :: "r"(dst), "l"(src) : "memory")
#define CP_COMMIT() asm volatile("cp.async.commit_group;" ::: "memory")
#define CP_WAIT(n)  asm volatile("cp.async.wait_group %0;" :: "n"(n) : "memory")

#define LDSM_X4(r, addr) \
    asm volatile("ldmatrix.sync.aligned.m8n8.x4.shared.b16 {%0,%1,%2,%3}, [%4];" \
                 : "=r"((r)[0]), "=r"((r)[1]), "=r"((r)[2]), "=r"((r)[3]) : "r"(addr))

__device__ __forceinline__ void mma_bf16(float* d, const uint32_t* a, const uint32_t* b) {
    asm volatile(
        "mma.sync.aligned.m16n8k16.row.col.f32.bf16.bf16.f32 "
        "{%0,%1,%2,%3}, {%4,%5,%6,%7}, {%8,%9}, {%0,%1,%2,%3};"
        : "+f"(d[0]), "+f"(d[1]), "+f"(d[2]), "+f"(d[3])
        : "r"(a[0]), "r"(a[1]), "r"(a[2]), "r"(a[3]), "r"(b[0]), "r"(b[1]));
}

__device__ __forceinline__ float sigmoidf_(float v) {
    return 1.0f / (1.0f + __expf(-v));
}

// ---------------------------------------------------------------------------
// Combined conversion kernel:
//   blocks [0, 8192):      A = [x | h0]  -> gAhi/gAlo   (row-identity)
//   blocks [8192, 16384):  B = [wih|whh] -> gBhi/gBlo   (rows permuted j*4+g)
//   blocks [16384, 16400): permuted bias sum
// ---------------------------------------------------------------------------
__global__ __launch_bounds__(256)
void convert_all(const float* __restrict__ x,   const float* __restrict__ h0,
                 const float* __restrict__ wih, const float* __restrict__ whh,
                 const float* __restrict__ b_ih, const float* __restrict__ b_hh)
{
    const int bid = blockIdx.x;
    const int tid = threadIdx.x;

    if (bid >= 16384) {                       // bias
        const int np = (bid - 16384) * 256 + tid;        // 0..4095
        const int r = ((np & 3) << 10) | (np >> 2);      // orig row g*1024+j
        gBias[np] = b_ih[r] + b_hh[r];
        return;
    }

    const bool isA = (bid < 8192);
    const int idx = (isA ? bid : bid - 8192) * 256 + tid;  // 4-elem group id
    const int row = idx >> 9;                              // output row
    const int col = (idx & 511) << 2;                      // K column

    int srow = row;
    const float *s0, *s1;
    if (isA) { s0 = x; s1 = h0; }
    else     { s0 = wih; s1 = whh; srow = ((row & 3) << 10) | (row >> 2); }

    const float* src = (col < 1024) ? (s0 + (size_t)srow * 1024 + col)
                                    : (s1 + (size_t)srow * 1024 + (col - 1024));
    float4 v = *reinterpret_cast<const float4*>(src);
    float f[4] = {v.x, v.y, v.z, v.w};
    __nv_bfloat16 hb[4], lb[4];
    #pragma unroll
    for (int j = 0; j < 4; j++) {
        hb[j] = __float2bfloat16(f[j]);
        lb[j] = __float2bfloat16(f[j] - __bfloat162float(hb[j]));
    }
    __nv_bfloat16* hi = isA ? gAhi : gBhi;
    __nv_bfloat16* lo = isA ? gAlo : gBlo;
    const size_t o = (size_t)row * K_DIM + col;
    *reinterpret_cast<__nv_bfloat162*>(hi + o)     = __nv_bfloat162(hb[0], hb[1]);
    *reinterpret_cast<__nv_bfloat162*>(hi + o + 2) = __nv_bfloat162(hb[2], hb[3]);
    *reinterpret_cast<__nv_bfloat162*>(lo + o)     = __nv_bfloat162(lb[0], lb[1]);
    *reinterpret_cast<__nv_bfloat162*>(lo + o + 2) = __nv_bfloat162(lb[2], lb[3]);
}

// ---------------------------------------------------------------------------
// Stage loader: 4 tiles x 512 16B-chunks = 2048 chunks; 8 per thread.
// ---------------------------------------------------------------------------
__device__ __forceinline__ void load_stage(uint32_t sbase, int k0, int bm, int bn, int tid)
{
    #pragma unroll
    for (int i = 0; i < 8; i++) {
        const int idx  = tid + i * 256;
        const int tile = idx >> 9;
        const int r    = (idx & 511) >> 2;
        const int c    = idx & 3;
        const __nv_bfloat16* src =
            (tile == 0) ? gAhi : (tile == 1) ? gAlo : (tile == 2) ? gBhi : gBlo;
        const int rowbase = (tile < 2) ? bm : bn;
        const void* g = src + (size_t)(rowbase + r) * K_DIM + k0 + c * 8;
        const uint32_t dst = sbase + tile * TILE_BYTES + r * ROW_STRIDE + c * 16;
        CP_ASYNC16(dst, g);
    }
}

// ---------------------------------------------------------------------------
// Fused GEMM + LSTM epilogue.
//   gates = Ahi*Bhi^T + Ahi*Blo^T + Alo*Bhi^T  (gate-interleaved columns)
//   then per (b, j): c = sig(f)*c0 + sig(i)*tanh(g); h = sig(o)*tanh(c)
//   out[0..B*H) = h,  out[B*H..2*B*H) = c
// ---------------------------------------------------------------------------
__global__ __launch_bounds__(NTHREADS, 2)
void lstm_gemm_fused(const float* __restrict__ c0, float* __restrict__ out)
{
    extern __shared__ char smem[];
    const uint32_t sb = smem_u32(smem);
    const int tid  = threadIdx.x;
    const int wid  = tid >> 5;
    const int lane = tid & 31;
    const int warp_m = wid >> 1;    // 0..3
    const int warp_n = wid & 1;     // 0..1

    const int bm = blockIdx.y * BM;
    const int bn = blockIdx.x * BN;

    float acc[2][8][4];
    #pragma unroll
    for (int mt = 0; mt < 2; mt++)
        #pragma unroll
        for (int nt = 0; nt < 8; nt++)
            #pragma unroll
            for (int j = 0; j < 4; j++)
                acc[mt][nt][j] = 0.0f;

    const int a_row = warp_m * 32 + (lane & 15);
    const int a_kby = (lane >> 4) * 16;
    const int b_nrow = warp_n * 64 + ((lane >> 4) << 3) + (lane & 7);
    const int b_kby  = ((lane >> 3) & 1) * 16;

    // prologue: stage 0
    load_stage(sb, 0, bm, bn, tid);
    CP_COMMIT();

    for (int t = 0; t < NT; t++) {
        if (t + 1 < NT)
            load_stage(sb + ((t + 1) & 1) * STAGE_BYTES, (t + 1) * BK, bm, bn, tid);
        CP_COMMIT();
        CP_WAIT(1);
        __syncthreads();

        const uint32_t stage = sb + (t & 1) * STAGE_BYTES;

        #pragma unroll
        for (int ks = 0; ks < 2; ks++) {
            uint32_t a_hi[2][4], a_lo[2][4];
            #pragma unroll
            for (int mt = 0; mt < 2; mt++) {
                const uint32_t aa = stage + (a_row + mt * 16) * ROW_STRIDE + ks * 32 + a_kby;
                LDSM_X4(a_hi[mt], aa);
                LDSM_X4(a_lo[mt], aa + TILE_BYTES);
            }
            #pragma unroll
            for (int g = 0; g < 4; g++) {
                uint32_t b_hi[4], b_lo[4];
                const uint32_t ba = stage + 2 * TILE_BYTES
                                  + (b_nrow + g * 16) * ROW_STRIDE + ks * 32 + b_kby;
                LDSM_X4(b_hi, ba);
                LDSM_X4(b_lo, ba + TILE_BYTES);
                #pragma unroll
                for (int mt = 0; mt < 2; mt++)
                    #pragma unroll
                    for (int h = 0; h < 2; h++) {
                        float* d = acc[mt][g * 2 + h];
                        mma_bf16(d, a_hi[mt], &b_hi[h * 2]);
                        mma_bf16(d, a_hi[mt], &b_lo[h * 2]);
                        mma_bf16(d, a_lo[mt], &b_hi[h * 2]);
                    }
            }
        }
        __syncthreads();
    }

    // ---- fused LSTM epilogue ----
    // thread owns col pair c = colbase + q*2 + {0,1}, q = lane&3.
    // even q: gates (i,f) of j ; odd q: gates (g,o) of same j.
    const int q = lane & 3;
    const bool is_if = ((q & 1) == 0);

    float bsum[8][2];
    #pragma unroll
    for (int nt = 0; nt < 8; nt++) {
        const int c = bn + warp_n * 64 + nt * 8 + q * 2;
        bsum[nt][0] = gBias[c];
        bsum[nt][1] = gBias[c + 1];
    }

    #pragma unroll
    for (int mt = 0; mt < 2; mt++) {
        const int r0 = bm + warp_m * 32 + mt * 16 + (lane >> 2);
        #pragma unroll
        for (int nt = 0; nt < 8; nt++) {
            float v0 = acc[mt][nt][0] + bsum[nt][0];
            float v1 = acc[mt][nt][1] + bsum[nt][1];
            float v2 = acc[mt][nt][2] + bsum[nt][0];
            float v3 = acc[mt][nt][3] + bsum[nt][1];
            const float o0 = __shfl_xor_sync(0xffffffffu, v0, 1);
            const float o1 = __shfl_xor_sync(0xffffffffu, v1, 1);
            const float o2 = __shfl_xor_sync(0xffffffffu, v2, 1);
            const float o3 = __shfl_xor_sync(0xffffffffu, v3, 1);

            const float gi0 = is_if ? v0 : o0;
            const float gf0 = is_if ? v1 : o1;
            const float gg0 = is_if ? o0 : v0;
            const float go0 = is_if ? o1 : v1;
            const float gi1 = is_if ? v2 : o2;
            const float gf1 = is_if ? v3 : o3;
            const float gg1 = is_if ? o2 : v2;
            const float go1 = is_if ? o3 : v3;

            const int j = (bn >> 2) + warp_n * 16 + nt * 2 + (q >> 1);
            const float c0v0 = c0[(size_t)r0 * H_DIM + j];
            const float c0v1 = c0[(size_t)(r0 + 8) * H_DIM + j];

            const float cn0 = sigmoidf_(gf0) * c0v0 + sigmoidf_(gi0) * tanhf(gg0);
            const float cn1 = sigmoidf_(gf1) * c0v1 + sigmoidf_(gi1) * tanhf(gg1);
            const float hn0 = sigmoidf_(go0) * tanhf(cn0);
            const float hn1 = sigmoidf_(go1) * tanhf(cn1);

            if (is_if) {
                out[(size_t)r0 * H_DIM + j]       = hn0;
                out[(size_t)(r0 + 8) * H_DIM + j] = hn1;
            } else {
                out[(size_t)B_DIM * H_DIM + (size_t)r0 * H_DIM + j]       = cn0;
                out[(size_t)B_DIM * H_DIM + (size_t)(r0 + 8) * H_DIM + j] = cn1;
            }
        }
    }
}

// ---------------------------------------------------------------------------
// Launch
// ---------------------------------------------------------------------------
extern "C" void kernel_launch(void* const* d_in, const int* in_sizes, int n_in,
                              void* d_out, int out_size)
{
    const float* x    = (const float*)d_in[0];
    const float* h0   = (const float*)d_in[1];
    const float* c0   = (const float*)d_in[2];
    const float* wih  = (const float*)d_in[3];
    const float* whh  = (const float*)d_in[4];
    const float* b_ih = (const float*)d_in[5];
    const float* b_hh = (const float*)d_in[6];
    float* out = (float*)d_out;

    cudaFuncSetAttribute(lstm_gemm_fused,
                         cudaFuncAttributeMaxDynamicSharedMemorySize, SMEM_TOTAL);

    convert_all<<<16400, 256>>>(x, h0, wih, whh, b_ih, b_hh);

    dim3 grid(N_GATES / BN, B_DIM / BM);                 // (32, 32)
    lstm_gemm_fused<<<grid, NTHREADS, SMEM_TOTAL>>>(c0, out);
}

// round 5
// speedup vs baseline: 3.4859x; 1.1714x over previous
#include <cuda_runtime.h>
#include <cuda_bf16.h>
#include <cstdint>

// ---------------------------------------------------------------------------
// Problem constants
// ---------------------------------------------------------------------------
#define B_DIM 4096
#define H_DIM 1024
#define N_GATES 4096       // 4*H
#define K_DIM  2048        // D + H

// GEMM tiling
#define BM 128
#define BN 128
#define BK 32
#define STAGES 3
#define NT (K_DIM / BK)    // 64 k-tiles
#define NTHREADS 256

// smem: per stage 4 tiles (Ahi, Alo, Bhi, Blo): 128 rows x 64B, XOR-swizzled.
#define TILE_BYTES 8192
#define STAGE_BYTES (4 * TILE_BYTES)          // 32768
#define SMEM_TOTAL (STAGES * STAGE_BYTES)     // 98304 -> 2 CTAs/SM

// ---------------------------------------------------------------------------
// Scratch (device globals; no runtime allocation)
// gB* hold the GATE-INTERLEAVED weight layout: row n' = j*4 + g  (orig g*H + j)
// ---------------------------------------------------------------------------
__device__ __nv_bfloat16 gAhi[(size_t)B_DIM * K_DIM];
__device__ __nv_bfloat16 gAlo[(size_t)B_DIM * K_DIM];
__device__ __nv_bfloat16 gBhi[(size_t)N_GATES * K_DIM];
__device__ __nv_bfloat16 gBlo[(size_t)N_GATES * K_DIM];
__device__ float gBias[N_GATES];   // permuted b_ih + b_hh

// ---------------------------------------------------------------------------
// PTX helpers (sm_80+ portable)
// ---------------------------------------------------------------------------
__device__ __forceinline__ uint32_t smem_u32(const void* p) {
    uint32_t a;
    asm("{ .reg .u64 t; cvta.to.shared.u64 t, %1; cvt.u32.u64 %0, t; }" : "=r"(a) : "l"(p));
    return a;
}

#define CP_ASYNC16(dst, src) \
    asm volatile("cp.async.cg.shared.global [%0], [%1], 16;" \
                 :: "r"(dst), "l"(src) : "memory")
#define CP_COMMIT() asm volatile("cp.async.commit_group;" ::: "memory")
#define CP_WAIT(n)  asm volatile("cp.async.wait_group %0;" :: "n"(n) : "memory")

#define LDSM_X4(r, addr) \
    asm volatile("ldmatrix.sync.aligned.m8n8.x4.shared.b16 {%0,%1,%2,%3}, [%4];" \
                 : "=r"((r)[0]), "=r"((r)[1]), "=r"((r)[2]), "=r"((r)[3]) : "r"(addr))

__device__ __forceinline__ void mma_bf16(float* d, const uint32_t* a, const uint32_t* b) {
    asm volatile(
        "mma.sync.aligned.m16n8k16.row.col.f32.bf16.bf16.f32 "
        "{%0,%1,%2,%3}, {%4,%5,%6,%7}, {%8,%9}, {%0,%1,%2,%3};"
        : "+f"(d[0]), "+f"(d[1]), "+f"(d[2]), "+f"(d[3])
        : "r"(a[0]), "r"(a[1]), "r"(a[2]), "r"(a[3]), "r"(b[0]), "r"(b[1]));
}

__device__ __forceinline__ float sigmoidf_(float v) {
    return 1.0f / (1.0f + __expf(-v));
}

// ---------------------------------------------------------------------------
// Combined conversion kernel:
//   blocks [0, 8192):      A = [x | h0]  -> gAhi/gAlo   (row-identity)
//   blocks [8192, 16384):  B = [wih|whh] -> gBhi/gBlo   (rows permuted j*4+g)
//   blocks [16384, 16400): permuted bias sum
// ---------------------------------------------------------------------------
__global__ __launch_bounds__(256)
void convert_all(const float* __restrict__ x,   const float* __restrict__ h0,
                 const float* __restrict__ wih, const float* __restrict__ whh,
                 const float* __restrict__ b_ih, const float* __restrict__ b_hh)
{
    const int bid = blockIdx.x;
    const int tid = threadIdx.x;

    if (bid >= 16384) {                       // bias
        const int np = (bid - 16384) * 256 + tid;        // 0..4095
        const int r = ((np & 3) << 10) | (np >> 2);      // orig row g*1024+j
        gBias[np] = b_ih[r] + b_hh[r];
        return;
    }

    const bool isA = (bid < 8192);
    const int idx = (isA ? bid : bid - 8192) * 256 + tid;  // 4-elem group id
    const int row = idx >> 9;                              // output row
    const int col = (idx & 511) << 2;                      // K column

    int srow = row;
    const float *s0, *s1;
    if (isA) { s0 = x; s1 = h0; }
    else     { s0 = wih; s1 = whh; srow = ((row & 3) << 10) | (row >> 2); }

    const float* src = (col < 1024) ? (s0 + (size_t)srow * 1024 + col)
                                    : (s1 + (size_t)srow * 1024 + (col - 1024));
    float4 v = *reinterpret_cast<const float4*>(src);
    float f[4] = {v.x, v.y, v.z, v.w};
    __nv_bfloat16 hb[4], lb[4];
    #pragma unroll
    for (int j = 0; j < 4; j++) {
        hb[j] = __float2bfloat16(f[j]);
        lb[j] = __float2bfloat16(f[j] - __bfloat162float(hb[j]));
    }
    __nv_bfloat16* hi = isA ? gAhi : gBhi;
    __nv_bfloat16* lo = isA ? gAlo : gBlo;
    const size_t o = (size_t)row * K_DIM + col;
    *reinterpret_cast<__nv_bfloat162*>(hi + o)     = __nv_bfloat162(hb[0], hb[1]);
    *reinterpret_cast<__nv_bfloat162*>(hi + o + 2) = __nv_bfloat162(hb[2], hb[3]);
    *reinterpret_cast<__nv_bfloat162*>(lo + o)     = __nv_bfloat162(lb[0], lb[1]);
    *reinterpret_cast<__nv_bfloat162*>(lo + o + 2) = __nv_bfloat162(lb[2], lb[3]);
}

// ---------------------------------------------------------------------------
// Fused GEMM + LSTM epilogue.
//   gates = Ahi*Bhi^T + Ahi*Blo^T + Alo*Bhi^T  (gate-interleaved columns)
//   then per (b, j): c = sig(f)*c0 + sig(i)*tanh(g); h = sig(o)*tanh(c)
//   out[0..B*H) = h,  out[B*H..2*B*H) = c
//
// SMEM tile layout: 128 rows x 4 16B-chunks, chunk' = chunk ^ ((row>>1)&3).
// Conflict-free for both cp.async 16B stores and ldmatrix reads.
// ---------------------------------------------------------------------------
__global__ __launch_bounds__(NTHREADS, 2)
void lstm_gemm_fused(const float* __restrict__ c0, float* __restrict__ out)
{
    extern __shared__ char smem[];
    const uint32_t sb = smem_u32(smem);
    const int tid  = threadIdx.x;
    const int wid  = tid >> 5;
    const int lane = tid & 31;
    const int warp_m = wid >> 1;    // 0..3
    const int warp_n = wid & 1;     // 0..1

    const int bm = blockIdx.y * BM;
    const int bn = blockIdx.x * BN;

    float acc[2][8][4];
    #pragma unroll
    for (int mt = 0; mt < 2; mt++)
        #pragma unroll
        for (int nt = 0; nt < 8; nt++)
            #pragma unroll
            for (int j = 0; j < 4; j++)
                acc[mt][nt][j] = 0.0f;

    // ---- ldmatrix addressing (lane-constant pieces hoisted) ----
    const int a_row = warp_m * 32 + (lane & 15);
    const int s_a   = (a_row >> 1) & 3;
    const int a_c0  = lane >> 4;                              // 0/1
    const int b_row = warp_n * 64 + ((lane >> 4) << 3) + (lane & 7);
    const int s_b   = (b_row >> 1) & 3;
    const int b_c0  = (lane >> 3) & 1;

    // ---- cp.async addressing: tile index is compile-time; row/chunk from tid ----
    const int r0 = tid >> 2;                 // 0..63
    const int cc = tid & 3;                  // 16B chunk
    const uint32_t dstoff = (uint32_t)(r0 * 64 + ((cc ^ ((r0 >> 1) & 3)) << 4));
    const __nv_bfloat16* pAhi = gAhi + (size_t)(bm + r0) * K_DIM + cc * 8;
    const __nv_bfloat16* pAlo = gAlo + (size_t)(bm + r0) * K_DIM + cc * 8;
    const __nv_bfloat16* pBhi = gBhi + (size_t)(bn + r0) * K_DIM + cc * 8;
    const __nv_bfloat16* pBlo = gBlo + (size_t)(bn + r0) * K_DIM + cc * 8;
    const size_t HSTEP = (size_t)64 * K_DIM;   // +64 rows

    #define LOAD_STAGE(bufidx, k0) do {                                         \
        const uint32_t s_ = sb + (bufidx) * STAGE_BYTES + dstoff;               \
        CP_ASYNC16(s_,                        pAhi + (k0));                     \
        CP_ASYNC16(s_ + 4096,                 pAhi + (k0) + HSTEP);             \
        CP_ASYNC16(s_ + TILE_BYTES,           pAlo + (k0));                     \
        CP_ASYNC16(s_ + TILE_BYTES + 4096,    pAlo + (k0) + HSTEP);             \
        CP_ASYNC16(s_ + 2*TILE_BYTES,         pBhi + (k0));                     \
        CP_ASYNC16(s_ + 2*TILE_BYTES + 4096,  pBhi + (k0) + HSTEP);             \
        CP_ASYNC16(s_ + 3*TILE_BYTES,         pBlo + (k0));                     \
        CP_ASYNC16(s_ + 3*TILE_BYTES + 4096,  pBlo + (k0) + HSTEP);             \
    } while (0)

    // prologue: stages 0,1
    LOAD_STAGE(0, 0);
    CP_COMMIT();
    LOAD_STAGE(1, BK);
    CP_COMMIT();

    int cbuf = 0, lbuf = 2;
    for (int t = 0; t < NT; t++) {
        CP_WAIT(1);
        __syncthreads();
        if (t + 2 < NT) {
            const int k0 = (t + 2) * BK;
            LOAD_STAGE(lbuf, k0);
        }
        CP_COMMIT();

        const uint32_t stage = sb + cbuf * STAGE_BYTES;
        #pragma unroll
        for (int ks = 0; ks < 2; ks++) {
            uint32_t a_hi[2][4], a_lo[2][4];
            const int ca = ((ks * 2 + a_c0) ^ s_a) << 4;
            #pragma unroll
            for (int mt = 0; mt < 2; mt++) {
                const uint32_t aa = stage + (a_row + mt * 16) * 64 + ca;
                LDSM_X4(a_hi[mt], aa);
                LDSM_X4(a_lo[mt], aa + TILE_BYTES);
            }
            const int cb = ((ks * 2 + b_c0) ^ s_b) << 4;
            #pragma unroll
            for (int g = 0; g < 4; g++) {
                uint32_t b_hi[4], b_lo[4];
                const uint32_t ba = stage + 2 * TILE_BYTES + (b_row + g * 16) * 64 + cb;
                LDSM_X4(b_hi, ba);
                LDSM_X4(b_lo, ba + TILE_BYTES);
                #pragma unroll
                for (int mt = 0; mt < 2; mt++)
                    #pragma unroll
                    for (int h = 0; h < 2; h++) {
                        float* d = acc[mt][g * 2 + h];
                        mma_bf16(d, a_hi[mt], &b_hi[h * 2]);
                        mma_bf16(d, a_hi[mt], &b_lo[h * 2]);
                        mma_bf16(d, a_lo[mt], &b_hi[h * 2]);
                    }
            }
        }
        if (++cbuf == STAGES) cbuf = 0;
        if (++lbuf == STAGES) lbuf = 0;
    }

    // ---- fused LSTM epilogue ----
    const int q = lane & 3;
    const bool is_if = ((q & 1) == 0);

    float bsum[8][2];
    #pragma unroll
    for (int nt = 0; nt < 8; nt++) {
        const int c = bn + warp_n * 64 + nt * 8 + q * 2;
        bsum[nt][0] = gBias[c];
        bsum[nt][1] = gBias[c + 1];
    }

    #pragma unroll
    for (int mt = 0; mt < 2; mt++) {
        const int r = bm + warp_m * 32 + mt * 16 + (lane >> 2);
        #pragma unroll
        for (int nt = 0; nt < 8; nt++) {
            float v0 = acc[mt][nt][0] + bsum[nt][0];
            float v1 = acc[mt][nt][1] + bsum[nt][1];
            float v2 = acc[mt][nt][2] + bsum[nt][0];
            float v3 = acc[mt][nt][3] + bsum[nt][1];
            const float o0 = __shfl_xor_sync(0xffffffffu, v0, 1);
            const float o1 = __shfl_xor_sync(0xffffffffu, v1, 1);
            const float o2 = __shfl_xor_sync(0xffffffffu, v2, 1);
            const float o3 = __shfl_xor_sync(0xffffffffu, v3, 1);

            const float gi0 = is_if ? v0 : o0;
            const float gf0 = is_if ? v1 : o1;
            const float gg0 = is_if ? o0 : v0;
            const float go0 = is_if ? o1 : v1;
            const float gi1 = is_if ? v2 : o2;
            const float gf1 = is_if ? v3 : o3;
            const float gg1 = is_if ? o2 : v2;
            const float go1 = is_if ? o3 : v3;

            const int j = (bn >> 2) + warp_n * 16 + nt * 2 + (q >> 1);
            const float c0v0 = c0[(size_t)r * H_DIM + j];
            const float c0v1 = c0[(size_t)(r + 8) * H_DIM + j];

            const float cn0 = sigmoidf_(gf0) * c0v0 + sigmoidf_(gi0) * tanhf(gg0);
            const float cn1 = sigmoidf_(gf1) * c0v1 + sigmoidf_(gi1) * tanhf(gg1);
            const float hn0 = sigmoidf_(go0) * tanhf(cn0);
            const float hn1 = sigmoidf_(go1) * tanhf(cn1);

            if (is_if) {
                out[(size_t)r * H_DIM + j]       = hn0;
                out[(size_t)(r + 8) * H_DIM + j] = hn1;
            } else {
                out[(size_t)B_DIM * H_DIM + (size_t)r * H_DIM + j]       = cn0;
                out[(size_t)B_DIM * H_DIM + (size_t)(r + 8) * H_DIM + j] = cn1;
            }
        }
    }
    #undef LOAD_STAGE
}

// ---------------------------------------------------------------------------
// Launch
// ---------------------------------------------------------------------------
extern "C" void kernel_launch(void* const* d_in, const int* in_sizes, int n_in,
                              void* d_out, int out_size)
{
    const float* x    = (const float*)d_in[0];
    const float* h0   = (const float*)d_in[1];
    const float* c0   = (const float*)d_in[2];
    const float* wih  = (const float*)d_in[3];
    const float* whh  = (const float*)d_in[4];
    const float* b_ih = (const float*)d_in[5];
    const float* b_hh = (const float*)d_in[6];
    float* out = (float*)d_out;

    cudaFuncSetAttribute(lstm_gemm_fused,
                         cudaFuncAttributeMaxDynamicSharedMemorySize, SMEM_TOTAL);

    convert_all<<<16400, 256>>>(x, h0, wih, whh, b_ih, b_hh);

    dim3 grid(N_GATES / BN, B_DIM / BM);                 // (32, 32)
    lstm_gemm_fused<<<grid, NTHREADS, SMEM_TOTAL>>>(c0, out);
}

// round 6
// speedup vs baseline: 3.5270x; 1.0118x over previous
#include <cuda_runtime.h>
#include <cuda_bf16.h>
#include <cstdint>

// ---------------------------------------------------------------------------
// Problem constants
// ---------------------------------------------------------------------------
#define B_DIM 4096
#define H_DIM 1024
#define N_GATES 4096       // 4*H
#define K_DIM  2048        // D + H

// GEMM tiling
#define BM 128
#define BN 128
#define BK 32
#define STAGES 3
#define NT (K_DIM / BK)    // 64 k-tiles
#define NTHREADS 256

// smem: per stage 4 tiles (Ahi, Alo, Bhi, Blo): 128 rows x 64B, XOR-swizzled.
#define TILE_BYTES 8192
#define STAGE_BYTES (4 * TILE_BYTES)          // 32768
#define SMEM_TOTAL (STAGES * STAGE_BYTES)     // 98304 -> 2 CTAs/SM

// ---------------------------------------------------------------------------
// Scratch (device globals; no runtime allocation)
// gB* hold the GATE-INTERLEAVED weight layout: row n' = j*4 + g  (orig g*H + j)
// ---------------------------------------------------------------------------
__device__ __nv_bfloat16 gAhi[(size_t)B_DIM * K_DIM];
__device__ __nv_bfloat16 gAlo[(size_t)B_DIM * K_DIM];
__device__ __nv_bfloat16 gBhi[(size_t)N_GATES * K_DIM];
__device__ __nv_bfloat16 gBlo[(size_t)N_GATES * K_DIM];
__device__ float gBias[N_GATES];   // permuted b_ih + b_hh

// ---------------------------------------------------------------------------
// PTX helpers (sm_80+ portable)
// ---------------------------------------------------------------------------
__device__ __forceinline__ uint32_t smem_u32(const void* p) {
    uint32_t a;
    asm("{ .reg .u64 t; cvta.to.shared.u64 t, %1; cvt.u32.u64 %0, t; }" : "=r"(a) : "l"(p));
    return a;
}

#define CP_ASYNC16(dst, src) \
    asm volatile("cp.async.cg.shared.global [%0], [%1], 16;" \
                 :: "r"(dst), "l"(src) : "memory")
#define CP_COMMIT() asm volatile("cp.async.commit_group;" ::: "memory")
#define CP_WAIT(n)  asm volatile("cp.async.wait_group %0;" :: "n"(n) : "memory")

#define LDSM_X4(r, addr) \
    asm volatile("ldmatrix.sync.aligned.m8n8.x4.shared.b16 {%0,%1,%2,%3}, [%4];" \
                 : "=r"((r)[0]), "=r"((r)[1]), "=r"((r)[2]), "=r"((r)[3]) : "r"(addr))

__device__ __forceinline__ void mma_bf16(float* d, const uint32_t* a, const uint32_t* b) {
    asm volatile(
        "mma.sync.aligned.m16n8k16.row.col.f32.bf16.bf16.f32 "
        "{%0,%1,%2,%3}, {%4,%5,%6,%7}, {%8,%9}, {%0,%1,%2,%3};"
        : "+f"(d[0]), "+f"(d[1]), "+f"(d[2]), "+f"(d[3])
        : "r"(a[0]), "r"(a[1]), "r"(a[2]), "r"(a[3]), "r"(b[0]), "r"(b[1]));
}

__device__ __forceinline__ float sigmoidf_(float v) {
    return 1.0f / (1.0f + __expf(-v));
}

// ---------------------------------------------------------------------------
// Combined conversion kernel:
//   blocks [0, 8192):      A = [x | h0]  -> gAhi/gAlo   (row-identity)
//   blocks [8192, 16384):  B = [wih|whh] -> gBhi/gBlo   (rows permuted j*4+g)
//   blocks [16384, 16400): permuted bias sum
// ---------------------------------------------------------------------------
__global__ __launch_bounds__(256)
void convert_all(const float* __restrict__ x,   const float* __restrict__ h0,
                 const float* __restrict__ wih, const float* __restrict__ whh,
                 const float* __restrict__ b_ih, const float* __restrict__ b_hh)
{
    const int bid = blockIdx.x;
    const int tid = threadIdx.x;

    if (bid >= 16384) {                       // bias
        const int np = (bid - 16384) * 256 + tid;        // 0..4095
        const int r = ((np & 3) << 10) | (np >> 2);      // orig row g*1024+j
        gBias[np] = b_ih[r] + b_hh[r];
        return;
    }

    const bool isA = (bid < 8192);
    const int idx = (isA ? bid : bid - 8192) * 256 + tid;  // 4-elem group id
    const int row = idx >> 9;                              // output row
    const int col = (idx & 511) << 2;                      // K column

    int srow = row;
    const float *s0, *s1;
    if (isA) { s0 = x; s1 = h0; }
    else     { s0 = wih; s1 = whh; srow = ((row & 3) << 10) | (row >> 2); }

    const float* src = (col < 1024) ? (s0 + (size_t)srow * 1024 + col)
                                    : (s1 + (size_t)srow * 1024 + (col - 1024));
    float4 v = *reinterpret_cast<const float4*>(src);
    float f[4] = {v.x, v.y, v.z, v.w};
    __nv_bfloat16 hb[4], lb[4];
    #pragma unroll
    for (int j = 0; j < 4; j++) {
        hb[j] = __float2bfloat16(f[j]);
        lb[j] = __float2bfloat16(f[j] - __bfloat162float(hb[j]));
    }
    __nv_bfloat16* hi = isA ? gAhi : gBhi;
    __nv_bfloat16* lo = isA ? gAlo : gBlo;
    const size_t o = (size_t)row * K_DIM + col;
    *reinterpret_cast<__nv_bfloat162*>(hi + o)     = __nv_bfloat162(hb[0], hb[1]);
    *reinterpret_cast<__nv_bfloat162*>(hi + o + 2) = __nv_bfloat162(hb[2], hb[3]);
    *reinterpret_cast<__nv_bfloat162*>(lo + o)     = __nv_bfloat162(lb[0], lb[1]);
    *reinterpret_cast<__nv_bfloat162*>(lo + o + 2) = __nv_bfloat162(lb[2], lb[3]);
}

// ---------------------------------------------------------------------------
// Fused GEMM + LSTM epilogue.
//   gates = Ahi*Bhi^T + Ahi*Blo^T + Alo*Bhi^T  (gate-interleaved columns)
//   then per (b, j): c = sig(f)*c0 + sig(i)*tanh(g); h = sig(o)*tanh(c)
//   out[0..B*H) = h,  out[B*H..2*B*H) = c
//
// SMEM tile layout: 128 rows x 4 16B-chunks, chunk' = chunk ^ ((row>>1)&3).
// Conflict-free for both cp.async 16B stores and ldmatrix reads.
// ---------------------------------------------------------------------------
__global__ __launch_bounds__(NTHREADS, 2)
void lstm_gemm_fused(const float* __restrict__ c0, float* __restrict__ out)
{
    extern __shared__ char smem[];
    const uint32_t sb = smem_u32(smem);
    const int tid  = threadIdx.x;
    const int wid  = tid >> 5;
    const int lane = tid & 31;
    const int warp_m = wid >> 1;    // 0..3
    const int warp_n = wid & 1;     // 0..1

    const int bm = blockIdx.y * BM;
    const int bn = blockIdx.x * BN;

    float acc[2][8][4];
    #pragma unroll
    for (int mt = 0; mt < 2; mt++)
        #pragma unroll
        for (int nt = 0; nt < 8; nt++)
            #pragma unroll
            for (int j = 0; j < 4; j++)
                acc[mt][nt][j] = 0.0f;

    // ---- ldmatrix addressing (lane-constant pieces hoisted) ----
    const int a_row = warp_m * 32 + (lane & 15);
    const int s_a   = (a_row >> 1) & 3;
    const int a_c0  = lane >> 4;                              // 0/1
    const int b_row = warp_n * 64 + ((lane >> 4) << 3) + (lane & 7);
    const int s_b   = (b_row >> 1) & 3;
    const int b_c0  = (lane >> 3) & 1;

    // ---- cp.async addressing: tile index is compile-time; row/chunk from tid ----
    const int r0 = tid >> 2;                 // 0..63
    const int cc = tid & 3;                  // 16B chunk
    const uint32_t dstoff = (uint32_t)(r0 * 64 + ((cc ^ ((r0 >> 1) & 3)) << 4));
    const __nv_bfloat16* pAhi = gAhi + (size_t)(bm + r0) * K_DIM + cc * 8;
    const __nv_bfloat16* pAlo = gAlo + (size_t)(bm + r0) * K_DIM + cc * 8;
    const __nv_bfloat16* pBhi = gBhi + (size_t)(bn + r0) * K_DIM + cc * 8;
    const __nv_bfloat16* pBlo = gBlo + (size_t)(bn + r0) * K_DIM + cc * 8;
    const size_t HSTEP = (size_t)64 * K_DIM;   // +64 rows

    #define LOAD_STAGE(bufidx, k0) do {                                         \
        const uint32_t s_ = sb + (bufidx) * STAGE_BYTES + dstoff;               \
        CP_ASYNC16(s_,                        pAhi + (k0));                     \
        CP_ASYNC16(s_ + 4096,                 pAhi + (k0) + HSTEP);             \
        CP_ASYNC16(s_ + TILE_BYTES,           pAlo + (k0));                     \
        CP_ASYNC16(s_ + TILE_BYTES + 4096,    pAlo + (k0) + HSTEP);             \
        CP_ASYNC16(s_ + 2*TILE_BYTES,         pBhi + (k0));                     \
        CP_ASYNC16(s_ + 2*TILE_BYTES + 4096,  pBhi + (k0) + HSTEP);             \
        CP_ASYNC16(s_ + 3*TILE_BYTES,         pBlo + (k0));                     \
        CP_ASYNC16(s_ + 3*TILE_BYTES + 4096,  pBlo + (k0) + HSTEP);             \
    } while (0)

    // prologue: stages 0,1
    LOAD_STAGE(0, 0);
    CP_COMMIT();
    LOAD_STAGE(1, BK);
    CP_COMMIT();

    int cbuf = 0, lbuf = 2;
    for (int t = 0; t < NT; t++) {
        CP_WAIT(1);
        __syncthreads();
        if (t + 2 < NT) {
            const int k0 = (t + 2) * BK;
            LOAD_STAGE(lbuf, k0);
        }
        CP_COMMIT();

        const uint32_t stage = sb + cbuf * STAGE_BYTES;
        #pragma unroll
        for (int ks = 0; ks < 2; ks++) {
            uint32_t a_hi[2][4], a_lo[2][4];
            const int ca = ((ks * 2 + a_c0) ^ s_a) << 4;
            #pragma unroll
            for (int mt = 0; mt < 2; mt++) {
                const uint32_t aa = stage + (a_row + mt * 16) * 64 + ca;
                LDSM_X4(a_hi[mt], aa);
                LDSM_X4(a_lo[mt], aa + TILE_BYTES);
            }
            const int cb = ((ks * 2 + b_c0) ^ s_b) << 4;
            #pragma unroll
            for (int g = 0; g < 4; g++) {
                uint32_t b_hi[4], b_lo[4];
                const uint32_t ba = stage + 2 * TILE_BYTES + (b_row + g * 16) * 64 + cb;
                LDSM_X4(b_hi, ba);
                LDSM_X4(b_lo, ba + TILE_BYTES);
                // Pass-major issue order: accumulator reuse distance = 4 MMAs
                // (was 1), covering the HMMA accumulate RAW latency.
                #pragma unroll
                for (int mt = 0; mt < 2; mt++)
                    #pragma unroll
                    for (int h = 0; h < 2; h++)
                        mma_bf16(acc[mt][g * 2 + h], a_hi[mt], &b_hi[h * 2]);
                #pragma unroll
                for (int mt = 0; mt < 2; mt++)
                    #pragma unroll
                    for (int h = 0; h < 2; h++)
                        mma_bf16(acc[mt][g * 2 + h], a_hi[mt], &b_lo[h * 2]);
                #pragma unroll
                for (int mt = 0; mt < 2; mt++)
                    #pragma unroll
                    for (int h = 0; h < 2; h++)
                        mma_bf16(acc[mt][g * 2 + h], a_lo[mt], &b_hi[h * 2]);
            }
        }
        if (++cbuf == STAGES) cbuf = 0;
        if (++lbuf == STAGES) lbuf = 0;
    }

    // ---- fused LSTM epilogue ----
    const int q = lane & 3;
    const bool is_if = ((q & 1) == 0);

    float bsum[8][2];
    #pragma unroll
    for (int nt = 0; nt < 8; nt++) {
        const int c = bn + warp_n * 64 + nt * 8 + q * 2;
        bsum[nt][0] = gBias[c];
        bsum[nt][1] = gBias[c + 1];
    }

    #pragma unroll
    for (int mt = 0; mt < 2; mt++) {
        const int r = bm + warp_m * 32 + mt * 16 + (lane >> 2);
        #pragma unroll
        for (int nt = 0; nt < 8; nt++) {
            float v0 = acc[mt][nt][0] + bsum[nt][0];
            float v1 = acc[mt][nt][1] + bsum[nt][1];
            float v2 = acc[mt][nt][2] + bsum[nt][0];
            float v3 = acc[mt][nt][3] + bsum[nt][1];
            const float o0 = __shfl_xor_sync(0xffffffffu, v0, 1);
            const float o1 = __shfl_xor_sync(0xffffffffu, v1, 1);
            const float o2 = __shfl_xor_sync(0xffffffffu, v2, 1);
            const float o3 = __shfl_xor_sync(0xffffffffu, v3, 1);

            const float gi0 = is_if ? v0 : o0;
            const float gf0 = is_if ? v1 : o1;
            const float gg0 = is_if ? o0 : v0;
            const float go0 = is_if ? o1 : v1;
            const float gi1 = is_if ? v2 : o2;
            const float gf1 = is_if ? v3 : o3;
            const float gg1 = is_if ? o2 : v2;
            const float go1 = is_if ? o3 : v3;

            const int j = (bn >> 2) + warp_n * 16 + nt * 2 + (q >> 1);
            const float c0v0 = c0[(size_t)r * H_DIM + j];
            const float c0v1 = c0[(size_t)(r + 8) * H_DIM + j];

            const float cn0 = sigmoidf_(gf0) * c0v0 + sigmoidf_(gi0) * tanhf(gg0);
            const float cn1 = sigmoidf_(gf1) * c0v1 + sigmoidf_(gi1) * tanhf(gg1);
            const float hn0 = sigmoidf_(go0) * tanhf(cn0);
            const float hn1 = sigmoidf_(go1) * tanhf(cn1);

            if (is_if) {
                out[(size_t)r * H_DIM + j]       = hn0;
                out[(size_t)(r + 8) * H_DIM + j] = hn1;
            } else {
                out[(size_t)B_DIM * H_DIM + (size_t)r * H_DIM + j]       = cn0;
                out[(size_t)B_DIM * H_DIM + (size_t)(r + 8) * H_DIM + j] = cn1;
            }
        }
    }
    #undef LOAD_STAGE
}

// ---------------------------------------------------------------------------
// Launch
// ---------------------------------------------------------------------------
extern "C" void kernel_launch(void* const* d_in, const int* in_sizes, int n_in,
                              void* d_out, int out_size)
{
    const float* x    = (const float*)d_in[0];
    const float* h0   = (const float*)d_in[1];
    const float* c0   = (const float*)d_in[2];
    const float* wih  = (const float*)d_in[3];
    const float* whh  = (const float*)d_in[4];
    const float* b_ih = (const float*)d_in[5];
    const float* b_hh = (const float*)d_in[6];
    float* out = (float*)d_out;

    cudaFuncSetAttribute(lstm_gemm_fused,
                         cudaFuncAttributeMaxDynamicSharedMemorySize, SMEM_TOTAL);

    convert_all<<<16400, 256>>>(x, h0, wih, whh, b_ih, b_hh);

    dim3 grid(N_GATES / BN, B_DIM / BM);                 // (32, 32)
    lstm_gemm_fused<<<grid, NTHREADS, SMEM_TOTAL>>>(c0, out);
}